// round 4
// baseline (speedup 1.0000x reference)
#include <cuda_runtime.h>
#include <math.h>

#define NMAX 150000
#define EMAX 150000
#define ITERS_T 31
#define HMAX 65536

// ---------------- device scratch (static allocations only) ----------------
__device__ float g_c[NMAX * 128];       // cell state c (h lives in d_out)
__device__ float g_xh[HMAX * 384];      // per-has-input-node child_h merge accum (zero-init, self-cleaning)
__device__ float g_xfc[HMAX * 384];     // per-has-input-node f*c accum
__device__ int g_mnode[NMAX];           // has-input node ids, grouped by iteration
__device__ int g_xslot[NMAX];           // node -> dense accumulation slot
__device__ int g_hasin[NMAX];
__device__ int g_ep[EMAX], g_ec[EMAX], g_es[EMAX];   // mattering edge parent/child/slot, grouped by iter
__device__ int g_ecnt[ITERS_T + 1], g_ncnt[ITERS_T + 1];
__device__ int g_eoff[ITERS_T + 2], g_noff[ITERS_T + 2];
__device__ int g_ecur[ITERS_T + 1], g_ncur[ITERS_T + 1];

// ---------------- prep ----------------
__global__ void k_init(int n) {
    int i = blockIdx.x * blockDim.x + threadIdx.x;
    if (i < n) g_hasin[i] = 0;
    if (i <= ITERS_T) { g_ecnt[i] = 0; g_ncnt[i] = 0; g_ecur[i] = 0; g_ncur[i] = 0; }
}

// NOTE: adjacency / node_order / edge_order arrive as int32 (JAX x64 disabled).
__device__ __forceinline__ bool edge_matters(
    const int* __restrict__ adj, const int* __restrict__ no,
    const int* __restrict__ eo, int n, int i,
    int& sp, int& sc, int& slot, int& ti)
{
    int p = adj[3 * i], c = adj[3 * i + 1];
    if (!(p >= 0 && p < n && c >= 0 && c < n)) return false;   // valid
    int t = eo[i];
    if (t < 0 || t >= ITERS_T) return false;
    sp = p; sc = c;
    if (no[sp] != t) return false;       // parent must update at this iteration
    if (!(no[sc] < t)) return false;     // child h/c still zero otherwise -> no-op
    int s = adj[3 * i + 2] + 1;
    slot = s < 0 ? 0 : (s > 2 ? 2 : s);
    ti = t;
    return true;
}

__global__ void k_count(const int* __restrict__ adj, const int* __restrict__ no,
                        const int* __restrict__ eo, int n, int e) {
    int i = blockIdx.x * blockDim.x + threadIdx.x;
    if (i >= e) return;
    int sp, sc, slot, ti;
    if (!edge_matters(adj, no, eo, n, i, sp, sc, slot, ti)) return;
    atomicAdd(&g_ecnt[ti], 1);
    if (atomicExch(&g_hasin[sp], 1) == 0) atomicAdd(&g_ncnt[ti], 1);
}

__global__ void k_scan() {
    if (threadIdx.x == 0 && blockIdx.x == 0) {
        int se = 0, sn = 0;
        for (int t = 0; t < ITERS_T; t++) {
            g_eoff[t] = se; se += g_ecnt[t];
            g_noff[t] = sn; sn += g_ncnt[t];
        }
        g_eoff[ITERS_T] = se; g_noff[ITERS_T] = sn;
    }
}

__global__ void k_node_scatter(const int* __restrict__ no, int n) {
    int i = blockIdx.x * blockDim.x + threadIdx.x;
    if (i >= n) return;
    if (!g_hasin[i]) return;
    int t = no[i];
    if (t < 0 || t >= ITERS_T) return;
    int pos = g_noff[t] + atomicAdd(&g_ncur[t], 1);
    g_mnode[pos] = i;
    g_xslot[i] = pos < HMAX ? pos : HMAX - 1;
}

__global__ void k_edge_scatter(const int* __restrict__ adj, const int* __restrict__ no,
                               const int* __restrict__ eo, int n, int e) {
    int i = blockIdx.x * blockDim.x + threadIdx.x;
    if (i >= e) return;
    int sp, sc, slot, ti;
    if (!edge_matters(adj, no, eo, n, i, sp, sc, slot, ti)) return;
    int pos = g_eoff[ti] + atomicAdd(&g_ecur[ti], 1);
    g_ep[pos] = sp; g_ec[pos] = sc; g_es[pos] = slot;
}

// ---------------- simple pass: h,c for ALL nodes assuming zero child input --------------
// iou = forest @ W_iou + b_iou ; c = sig(i)*tanh(u) + b_c ; h = sig(o)*tanh(c)
// Tiled fp32 GEMM: 64 nodes x 32 gate-cols x 3 gates per block, K=128.
__global__ void __launch_bounds__(256) k_simple(
    const float* __restrict__ forest, const float* __restrict__ W_iou,
    const float* __restrict__ b_iou, const float* __restrict__ b_c,
    float* __restrict__ hout, int n)
{
    __shared__ float As[64][33];
    __shared__ float Bs[32 * 96];
    int tid = threadIdx.x;
    int bm = blockIdx.x, bj = blockIdx.y;
    int tm4 = (tid & 15) * 4;
    int tj2 = (tid >> 4) * 2;

    float acc[3][4][2];
#pragma unroll
    for (int g = 0; g < 3; g++)
#pragma unroll
        for (int nn = 0; nn < 4; nn++) { acc[g][nn][0] = 0.f; acc[g][nn][1] = 0.f; }

    for (int kc = 0; kc < 4; kc++) {
#pragma unroll
        for (int r = 0; r < 8; r++) {
            int l = r * 256 + tid;
            int m = l >> 5, k = l & 31;
            int node = bm * 64 + m; if (node >= n) node = n - 1;
            As[m][k] = forest[node * 128 + kc * 32 + k];
        }
#pragma unroll
        for (int r = 0; r < 12; r++) {
            int l = r * 256 + tid;
            int kk = l / 96, c = l - kk * 96;
            int g = c >> 5, jj = c & 31;
            Bs[l] = W_iou[(kc * 32 + kk) * 384 + g * 128 + bj * 32 + jj];
        }
        __syncthreads();
#pragma unroll
        for (int k = 0; k < 32; k++) {
            float b00 = Bs[k * 96 + tj2],      b01 = Bs[k * 96 + tj2 + 1];
            float b10 = Bs[k * 96 + 32 + tj2], b11 = Bs[k * 96 + 32 + tj2 + 1];
            float b20 = Bs[k * 96 + 64 + tj2], b21 = Bs[k * 96 + 64 + tj2 + 1];
#pragma unroll
            for (int nn = 0; nn < 4; nn++) {
                float a = As[tm4 + nn][k];
                acc[0][nn][0] += a * b00; acc[0][nn][1] += a * b01;
                acc[1][nn][0] += a * b10; acc[1][nn][1] += a * b11;
                acc[2][nn][0] += a * b20; acc[2][nn][1] += a * b21;
            }
        }
        __syncthreads();
    }
#pragma unroll
    for (int nn = 0; nn < 4; nn++) {
        int node = bm * 64 + tm4 + nn;
        if (node >= n) continue;
#pragma unroll
        for (int jj = 0; jj < 2; jj++) {
            int j = bj * 32 + tj2 + jj;
            float iv = acc[0][nn][jj] + b_iou[j];
            float ov = acc[1][nn][jj] + b_iou[128 + j];
            float uv = acc[2][nn][jj] + b_iou[256 + j];
            float cv = (1.f / (1.f + expf(-iv))) * tanhf(uv) + b_c[j];
            float hv = (1.f / (1.f + expf(-ov))) * tanhf(cv);
            g_c[node * 128 + j] = cv;
            hout[node * 128 + j] = hv;
        }
    }
}

// ---------------- per-iteration: mattering edges ----------------
// f = sigmoid(forest[p]@W_f + b_f + h[c]@U_f); accumulate child h and f*c into parent slot.
__global__ void __launch_bounds__(128) k_edge(
    const float* __restrict__ forest, const float* __restrict__ hbuf,
    const float* __restrict__ W_f, const float* __restrict__ b_f,
    const float* __restrict__ U_f, int t)
{
    __shared__ float sf[128], sh[128];
    int idx = g_eoff[t] + blockIdx.x;
    if (idx >= g_eoff[t + 1]) return;
    int p = g_ep[idx], ch = g_ec[idx], slot = g_es[idx];
    int xi = g_xslot[p];
    int j = threadIdx.x;
    sf[j] = forest[p * 128 + j];
    sh[j] = hbuf[ch * 128 + j];
    __syncthreads();
    float acc = b_f[j];
#pragma unroll 8
    for (int k = 0; k < 128; k++) acc += sf[k] * W_f[k * 128 + j];
#pragma unroll 8
    for (int k = 0; k < 128; k++) acc += sh[k] * U_f[k * 128 + j];
    float f = 1.f / (1.f + expf(-acc));
    float fc = f * g_c[ch * 128 + j];
    atomicAdd(&g_xh[xi * 384 + slot * 128 + j], sh[j]);
    atomicAdd(&g_xfc[xi * 384 + slot * 128 + j], fc);
}

// ---------------- per-iteration: has-input nodes (full recompute) ----------------
__global__ void __launch_bounds__(128) k_node(
    const float* __restrict__ forest, const float* __restrict__ W_iou,
    const float* __restrict__ b_iou, const float* __restrict__ U_iou,
    const float* __restrict__ W_c, const float* __restrict__ b_c,
    float* __restrict__ hbuf, int t)
{
    __shared__ float xin[512], yin[384];
    int pos = g_noff[t] + blockIdx.x;
    if (pos >= g_noff[t + 1]) return;
    int i = g_mnode[pos];
    int xi = g_xslot[i];
    int j = threadIdx.x;
    xin[j] = forest[i * 128 + j];
#pragma unroll
    for (int s = 0; s < 3; s++) {
        xin[128 + s * 128 + j] = g_xh[xi * 384 + s * 128 + j];
        yin[s * 128 + j]       = g_xfc[xi * 384 + s * 128 + j];
        g_xh[xi * 384 + s * 128 + j] = 0.f;   // self-clean for next replay
        g_xfc[xi * 384 + s * 128 + j] = 0.f;
    }
    __syncthreads();
    float aI = b_iou[j], aO = b_iou[128 + j], aU = b_iou[256 + j];
#pragma unroll 4
    for (int k = 0; k < 128; k++) {
        float v = xin[k];
        aI += v * W_iou[k * 384 + j];
        aO += v * W_iou[k * 384 + 128 + j];
        aU += v * W_iou[k * 384 + 256 + j];
    }
#pragma unroll 4
    for (int k = 0; k < 384; k++) {
        float v = xin[128 + k];
        aI += v * U_iou[k * 384 + j];
        aO += v * U_iou[k * 384 + 128 + j];
        aU += v * U_iou[k * 384 + 256 + j];
    }
    float aC = b_c[j];
#pragma unroll 4
    for (int k = 0; k < 384; k++) aC += yin[k] * W_c[k * 128 + j];
    float cv = (1.f / (1.f + expf(-aI))) * tanhf(aU) + aC;
    float hv = (1.f / (1.f + expf(-aO))) * tanhf(cv);
    g_c[i * 128 + j] = cv;
    hbuf[i * 128 + j] = hv;
}

// ---------------- launch ----------------
extern "C" void kernel_launch(void* const* d_in, const int* in_sizes, int n_in,
                              void* d_out, int out_size) {
    const float* forest = (const float*)d_in[0];
    const int*   adj    = (const int*)d_in[1];
    const int*   no     = (const int*)d_in[2];
    const int*   eo     = (const int*)d_in[3];
    const float* W_iou  = (const float*)d_in[4];
    const float* b_iou  = (const float*)d_in[5];
    const float* U_iou  = (const float*)d_in[6];
    const float* W_c    = (const float*)d_in[7];
    const float* b_c    = (const float*)d_in[8];
    const float* W_f    = (const float*)d_in[9];
    const float* b_f    = (const float*)d_in[10];
    const float* U_f    = (const float*)d_in[11];
    float* hout = (float*)d_out;

    int n = in_sizes[0] / 128;
    int e = in_sizes[1] / 3;

    int ginit = (n + 255) / 256; if (ginit < 1) ginit = 1;
    k_init<<<ginit, 256>>>(n);
    k_count<<<(e + 255) / 256, 256>>>(adj, no, eo, n, e);
    k_scan<<<1, 32>>>();
    k_node_scatter<<<(n + 255) / 256, 256>>>(no, n);
    k_edge_scatter<<<(e + 255) / 256, 256>>>(adj, no, eo, n, e);

    dim3 g5((n + 63) / 64, 4);
    k_simple<<<g5, 256>>>(forest, W_iou, b_iou, b_c, hout, n);

    for (int t = 0; t < ITERS_T; t++) {
        k_edge<<<1024, 128>>>(forest, hout, W_f, b_f, U_f, t);
        k_node<<<512, 128>>>(forest, W_iou, b_iou, U_iou, W_c, b_c, hout, t);
    }
}